// round 6
// baseline (speedup 1.0000x reference)
#include <cuda_runtime.h>
#include <cstdint>
#include <cstddef>

typedef unsigned long long ull;

#define BB 64
#define TT 1024
#define DD 256
#define UU 256
#define MM (BB*TT)          // 65536 rows for the input projection

// Scan weight split: KREG k-rows live in registers, KS k-rows streamed from SMEM
#define KREG 192
#define NWU  (KREG/2)       // 96 packed (k-pair) ull per thread in regs
#define KS   (UU-KREG)      // 64
#define NWS  (KS/2)         // 32 packed rows in dynamic SMEM (64 KB)

// NO __device__ globals in this version: xW scratch lives in d_out itself
// (identical shape [B,T,U] fp32; scan reads xw then overwrites with h).

// ---------------- packed f32x2 helpers ----------------
__device__ __forceinline__ ull fma2(ull a, ull b, ull c){
    ull d;
    asm("fma.rn.f32x2 %0, %1, %2, %3;" : "=l"(d) : "l"(a), "l"(b), "l"(c));
    return d;
}
__device__ __forceinline__ float2 unpack2(ull a){
    float2 r;
    asm("mov.b64 {%0, %1}, %2;" : "=f"(r.x), "=f"(r.y) : "l"(a));
    return r;
}
__device__ __forceinline__ ull pack2(float lo, float hi){
    ull p;
    asm("mov.b64 %0, {%1, %2};" : "=l"(p) : "f"(lo), "f"(hi));
    return p;
}

// ---------------- input projection GEMM: out[m][u] = sum_k X[m][k]*W_xh[k][u] + b[u] ----------------
#define GR 32   // rows per block

__device__ __forceinline__ void gemm_chunk(const float* xs, int cc, const ull* w, ull* acc){
    #pragma unroll
    for (int r = 0; r < GR; r++){
        const ulonglong2* xr = reinterpret_cast<const ulonglong2*>(xs + r*UU) + cc*4;
        #pragma unroll
        for (int j = 0; j < 4; j++){
            ulonglong2 xx = xr[j];                   // 4 consecutive x values (2 k-pairs), broadcast LDS
            acc[r] = fma2(xx.x, w[2*j],   acc[r]);
            acc[r] = fma2(xx.y, w[2*j+1], acc[r]);
        }
    }
}

// load packed weight pair (W[k][u], W[k+1][u]) straight from the fp32 matrix
__device__ __forceinline__ ull wload(const float* W, int k, int u){
    return pack2(W[(size_t)k*UU + u], W[(size_t)(k+1)*UU + u]);
}

__global__ void __launch_bounds__(256,1) gemm_kernel(const float* __restrict__ X,
                                                     const float* __restrict__ Wxh,
                                                     const float* __restrict__ bh,
                                                     float* __restrict__ out){
    __shared__ __align__(16) float xs[GR*UU];        // 32 KB x-tile
    const int u    = threadIdx.x;
    const int row0 = blockIdx.x * GR;

    {   // stage X tile (coalesced float4)
        const float4* Xv = reinterpret_cast<const float4*>(X + (size_t)row0*UU);
        float4* sv = reinterpret_cast<float4*>(xs);
        #pragma unroll
        for (int i = 0; i < (GR*UU/4)/256; i++)
            sv[threadIdx.x + i*256] = Xv[threadIdx.x + i*256];
    }
    float bias = bh[u];
    __syncthreads();

    ull acc[GR];
    #pragma unroll
    for (int r = 0; r < GR; r++) acc[r] = 0ULL;

    // 16 k-chunks of 16 k (8 packed pairs), weight pairs double-buffered from L2
    ull wcur[8], wnxt[8];
    #pragma unroll
    for (int j = 0; j < 8; j++) wcur[j] = wload(Wxh, 2*j, u);

    #pragma unroll 1
    for (int c = 0; c < 16; c += 2){
        #pragma unroll
        for (int j = 0; j < 8; j++) wnxt[j] = wload(Wxh, 2*((c+1)*8 + j), u);
        gemm_chunk(xs, c, wcur, acc);
        if (c + 2 < 16){
            #pragma unroll
            for (int j = 0; j < 8; j++) wcur[j] = wload(Wxh, 2*((c+2)*8 + j), u);
        }
        gemm_chunk(xs, c+1, wnxt, acc);
    }

    // write xW (pre-activation) into d_out — it doubles as the scan's input
    #pragma unroll
    for (int r = 0; r < GR; r++){
        float2 v = unpack2(acc[r]);
        out[(size_t)(row0 + r)*UU + u] = v.x + v.y + bias;
    }
}

// ---------------- sequential scan: one CTA per batch row ----------------
// Streamed W_hh rows: 64 KB dynamic smem (opt-in attribute, capture-safe).
extern __shared__ ull ws[];   // NWS*UU packed rows (65536 bytes)

__global__ void __launch_bounds__(256,1) scan_kernel(const float* __restrict__ Whh,
                                                     float* __restrict__ out){
    __shared__ __align__(16) float hbuf[2][UU];
    const int u = threadIdx.x;
    const int b = blockIdx.x;

    // register-resident W_hh rows (k in [0, KREG)), packed inline from fp32
    ull w[NWU];
    #pragma unroll
    for (int j = 0; j < NWU; j++) w[j] = wload(Whh, 2*j, u);

    // SMEM-resident W_hh rows (k in [KREG, 256))
    #pragma unroll
    for (int i = 0; i < NWS; i++) ws[i*UU + u] = wload(Whh, KREG + 2*i, u);

    hbuf[0][u] = 0.f;
    hbuf[1][u] = 0.f;
    __syncthreads();

    float* row = out + ((size_t)b*TT)*UU + u;   // holds xw on entry, h on exit

    int p = 0;
    #pragma unroll 1
    for (int t = 0; t < TT; t++){
        float xw = row[0];           // read the pre-activation written by the GEMM
        ull a0 = 0ULL, a1 = 0ULL;
        const ulonglong2* hv = reinterpret_cast<const ulonglong2*>(hbuf[p]);

        // register-weight part: 96 packed FMA2s (two independent chains)
        #pragma unroll
        for (int j = 0; j < NWU/2; j++){
            ulonglong2 hh = hv[j];                    // broadcast LDS.128: h[4j..4j+3]
            a0 = fma2(hh.x, w[2*j],   a0);
            a1 = fma2(hh.y, w[2*j+1], a1);
        }
        // SMEM-streamed weight part: 32 packed FMA2s
        #pragma unroll
        for (int j = 0; j < NWS/2; j++){
            ulonglong2 hh = hv[NWU/2 + j];
            a0 = fma2(hh.x, ws[(2*j)*UU + u],   a0);
            a1 = fma2(hh.y, ws[(2*j+1)*UU + u], a1);
        }

        float2 v0 = unpack2(a0), v1 = unpack2(a1);
        float h = tanhf((v0.x + v1.x) + (v0.y + v1.y) + xw);

        hbuf[p^1][u] = h;
        row[0] = h;                  // overwrite the same element with h_t
        __syncthreads();
        p ^= 1;
        row += UU;
    }
}

// ---------------- launch ----------------
extern "C" void kernel_launch(void* const* d_in, const int* in_sizes, int n_in,
                              void* d_out, int out_size){
    // Identify inputs by size, accepting BOTH element-count and byte-count
    // semantics; fall back to positional insertion order.
    int idx_inputs = -1, idx_b = -1;
    int widx[2] = {-1, -1}; int nw = 0;
    for (int i = 0; i < n_in; i++){
        long long sz = in_sizes[i];
        if      (sz == (long long)MM*DD || sz == (long long)MM*DD*4) idx_inputs = i;
        else if (sz == UU || sz == UU*4)                             idx_b = i;
        else if (nw < 2)                                             widx[nw++] = i;
    }

    const float *X, *bh, *Wxh, *Whh;
    if (idx_inputs >= 0 && idx_b >= 0 && nw == 2){
        X  = (const float*)d_in[idx_inputs];
        bh = (const float*)d_in[idx_b];
        if (idx_inputs < widx[0]){
            // insertion order: inputs, W_xh, W_hh, b_h
            Wxh = (const float*)d_in[widx[0]];
            Whh = (const float*)d_in[widx[1]];
        } else {
            // sorted order: W_hh, W_xh, b_h, inputs
            Whh = (const float*)d_in[widx[0]];
            Wxh = (const float*)d_in[widx[1]];
        }
    } else {
        X   = (const float*)d_in[0];
        Wxh = (const float*)d_in[1];
        Whh = (const float*)d_in[2];
        bh  = (const float*)d_in[3];
    }
    float* out = (float*)d_out;                 // [64,1024,256] fp32

    cudaFuncSetAttribute(scan_kernel, cudaFuncAttributeMaxDynamicSharedMemorySize, NWS*UU*8);

    gemm_kernel<<<MM/GR, 256>>>(X, Wxh, bh, out);
    scan_kernel<<<BB, 256, NWS*UU*8>>>(Whh, out);
}

// round 8
// speedup vs baseline: 1.1260x; 1.1260x over previous
#include <cuda_runtime.h>
#include <cstdint>
#include <cstddef>

typedef unsigned long long ull;

#define BB 64
#define TT 1024
#define DD 256
#define UU 256
#define MM (BB*TT)          // 65536 rows for the input projection

// ---------------- packed f32x2 helpers ----------------
__device__ __forceinline__ ull fma2(ull a, ull b, ull c){
    ull d;
    asm("fma.rn.f32x2 %0, %1, %2, %3;" : "=l"(d) : "l"(a), "l"(b), "l"(c));
    return d;
}
__device__ __forceinline__ float2 unpack2(ull a){
    float2 r;
    asm("mov.b64 {%0, %1}, %2;" : "=f"(r.x), "=f"(r.y) : "l"(a));
    return r;
}
__device__ __forceinline__ ull pack2(float lo, float hi){
    ull p;
    asm("mov.b64 %0, {%1, %2};" : "=l"(p) : "f"(lo), "f"(hi));
    return p;
}
__device__ __forceinline__ ull wload(const float* W, int k, int u){
    return pack2(W[(size_t)k*UU + u], W[(size_t)(k+1)*UU + u]);
}

// ---------------- cluster / mbarrier PTX helpers ----------------
__device__ __forceinline__ uint32_t smem_u32(const void* p){
    uint32_t a;
    asm("{ .reg .u64 t; cvta.to.shared.u64 t, %1; cvt.u32.u64 %0, t; }" : "=r"(a) : "l"(p));
    return a;
}
__device__ __forceinline__ uint32_t ctarank(){
    uint32_t r; asm("mov.u32 %0, %%cluster_ctarank;" : "=r"(r)); return r;
}
__device__ __forceinline__ void mbar_init(uint32_t a, uint32_t cnt){
    asm volatile("mbarrier.init.shared.b64 [%0], %1;" :: "r"(a), "r"(cnt) : "memory");
}
// arrive on the peer CTA's mbarrier at the same smem offset
// (explicit release at cluster scope so the preceding st.shared::cluster is
//  ordered before the arrive for the peer's acquire-wait)
__device__ __forceinline__ void mbar_arrive_peer(uint32_t local_addr, uint32_t peer){
    asm volatile(
        "{ .reg .b32 r; mapa.shared::cluster.u32 r, %0, %1;\n\t"
        "mbarrier.arrive.release.cluster.shared::cluster.b64 _, [r]; }"
        :: "r"(local_addr), "r"(peer) : "memory");
}
// store one float into the peer CTA's smem at the same offset
__device__ __forceinline__ void st_peer_f32(uint32_t local_addr, float v, uint32_t peer){
    asm volatile(
        "{ .reg .b32 r; mapa.shared::cluster.u32 r, %0, %2;\n\t"
        "st.shared::cluster.f32 [r], %1; }"
        :: "r"(local_addr), "f"(v), "r"(peer) : "memory");
}
// parity wait with cluster-scope acquire (orders peer's cluster stores)
__device__ __forceinline__ void mbar_wait_cluster(uint32_t addr, uint32_t parity){
    asm volatile(
        "{\n\t"
        ".reg .pred P;\n\t"
        "WL_%=:\n\t"
        "mbarrier.try_wait.parity.acquire.cluster.shared::cta.b64 P, [%0], %1, 0x989680;\n\t"
        "@P bra.uni WD_%=;\n\t"
        "bra.uni WL_%=;\n\t"
        "WD_%=:\n\t"
        "}" :: "r"(addr), "r"(parity) : "memory");
}
__device__ __forceinline__ void cluster_sync_(){
    asm volatile("barrier.cluster.arrive.aligned;" ::: "memory");
    asm volatile("barrier.cluster.wait.aligned;"   ::: "memory");
}

// ---------------- input projection GEMM (unchanged, passed R6) ----------------
#define GR 32   // rows per block

__device__ __forceinline__ void gemm_chunk(const float* xs, int cc, const ull* w, ull* acc){
    #pragma unroll
    for (int r = 0; r < GR; r++){
        const ulonglong2* xr = reinterpret_cast<const ulonglong2*>(xs + r*UU) + cc*4;
        #pragma unroll
        for (int j = 0; j < 4; j++){
            ulonglong2 xx = xr[j];
            acc[r] = fma2(xx.x, w[2*j],   acc[r]);
            acc[r] = fma2(xx.y, w[2*j+1], acc[r]);
        }
    }
}

__global__ void __launch_bounds__(256,1) gemm_kernel(const float* __restrict__ X,
                                                     const float* __restrict__ Wxh,
                                                     const float* __restrict__ bh,
                                                     float* __restrict__ out){
    __shared__ __align__(16) float xs[GR*UU];
    const int u    = threadIdx.x;
    const int row0 = blockIdx.x * GR;

    {
        const float4* Xv = reinterpret_cast<const float4*>(X + (size_t)row0*UU);
        float4* sv = reinterpret_cast<float4*>(xs);
        #pragma unroll
        for (int i = 0; i < (GR*UU/4)/256; i++)
            sv[threadIdx.x + i*256] = Xv[threadIdx.x + i*256];
    }
    float bias = bh[u];
    __syncthreads();

    ull acc[GR];
    #pragma unroll
    for (int r = 0; r < GR; r++) acc[r] = 0ULL;

    ull wcur[8], wnxt[8];
    #pragma unroll
    for (int j = 0; j < 8; j++) wcur[j] = wload(Wxh, 2*j, u);

    #pragma unroll 1
    for (int c = 0; c < 16; c += 2){
        #pragma unroll
        for (int j = 0; j < 8; j++) wnxt[j] = wload(Wxh, 2*((c+1)*8 + j), u);
        gemm_chunk(xs, c, wcur, acc);
        if (c + 2 < 16){
            #pragma unroll
            for (int j = 0; j < 8; j++) wcur[j] = wload(Wxh, 2*((c+2)*8 + j), u);
        }
        gemm_chunk(xs, c+1, wnxt, acc);
    }

    #pragma unroll
    for (int r = 0; r < GR; r++){
        float2 v = unpack2(acc[r]);
        out[(size_t)(row0 + r)*UU + u] = v.x + v.y + bias;   // xW pre-activation
    }
}

// ---------------- clustered scan: 2 CTAs per batch row (u-split), all weights in regs ----
// CTA pair (2b, 2b+1): rank r owns u in [r*128, r*128+128).
// 256 threads: u_loc = t&127, kh = t>>7 selects k-half [kh*128, kh*128+128).
// Weights: 64 packed f32x2 pairs = 128 regs/thread, fully register-resident.
__global__ void __launch_bounds__(256,1) __cluster_dims__(2,1,1)
scan2_kernel(const float* __restrict__ Whh, float* __restrict__ out){
    __shared__ __align__(16) float hbuf[2][UU];   // full h, double-buffered
    __shared__ float redbuf[128];                 // k-split partial
    __shared__ __align__(8) ull mbars[2];

    const int t     = threadIdx.x;
    const int u_loc = t & 127;
    const int kh    = t >> 7;                     // 0/1: which k-half this thread covers
    const uint32_t rank = ctarank();
    const uint32_t peer = rank ^ 1u;
    const int b      = blockIdx.x >> 1;
    const int u_glob = (int)rank*128 + u_loc;

    // load my 64 weight pairs: W_hh[kh*128 + 2j .. +1][u_glob]
    ull w[64];
    #pragma unroll
    for (int j = 0; j < 64; j++) w[j] = wload(Whh, kh*128 + 2*j, u_glob);

    const uint32_t mb0 = smem_u32(&mbars[0]);
    const uint32_t mb1 = smem_u32(&mbars[1]);
    if (t == 0){ mbar_init(mb0, 128); mbar_init(mb1, 128); }
    hbuf[0][t] = 0.f;                             // step 0 reads zeros
    __syncthreads();
    cluster_sync_();                              // peer mbar init visible before any remote arrive

    float* xrow = out + ((size_t)b*TT)*UU + u_glob;   // owners only (kh==0)

    // this CTA's threads with kh != rank read the REMOTE half of h each step
    const bool need_remote = ((uint32_t)kh != rank);

    #pragma unroll 1
    for (int tt = 0; tt < TT; tt++){
        // wait for exchange (tt-1) if my h-half comes from the peer
        if (tt > 0 && need_remote){
            int e = tt - 1;
            mbar_wait_cluster((e & 1) ? mb1 : mb0, (e >> 1) & 1);
        }

        float xw = 0.f;
        if (kh == 0) xw = xrow[0];                // prefetch pre-activation early

        const ulonglong2* hv =
            reinterpret_cast<const ulonglong2*>(&hbuf[tt & 1][kh*128]);
        ull a0 = 0ULL, a1 = 0ULL;
        #pragma unroll
        for (int j = 0; j < 32; j++){
            ulonglong2 hh = hv[j];                // broadcast LDS.128
            a0 = fma2(hh.x, w[2*j],   a0);
            a1 = fma2(hh.y, w[2*j+1], a1);
        }
        float2 v0 = unpack2(a0), v1 = unpack2(a1);
        float part = (v0.x + v0.y) + (v1.x + v1.y);

        if (kh == 1) redbuf[u_loc] = part;
        __syncthreads();                          // reduce barrier

        if (kh == 0){
            float h = tanhf(part + redbuf[u_loc] + xw);
            xrow[0] = h;                                      // final output
            if (tt + 1 < TT){                                 // exchange tt feeds step tt+1 only
                int q = (tt & 1) ^ 1;
                hbuf[q][u_glob] = h;                              // local half
                st_peer_f32(smem_u32(&hbuf[q][u_glob]), h, peer); // remote half
                mbar_arrive_peer((tt & 1) ? mb1 : mb0, peer);     // exchange tt (release)
            }
            xrow += UU;
        }
        __syncthreads();                          // local half visible to next step
    }

    // no CTA may exit while peer-targeted SMEM traffic could be in flight
    cluster_sync_();
}

// ---------------- launch ----------------
extern "C" void kernel_launch(void* const* d_in, const int* in_sizes, int n_in,
                              void* d_out, int out_size){
    int idx_inputs = -1, idx_b = -1;
    int widx[2] = {-1, -1}; int nw = 0;
    for (int i = 0; i < n_in; i++){
        long long sz = in_sizes[i];
        if      (sz == (long long)MM*DD || sz == (long long)MM*DD*4) idx_inputs = i;
        else if (sz == UU || sz == UU*4)                             idx_b = i;
        else if (nw < 2)                                             widx[nw++] = i;
    }

    const float *X, *bh, *Wxh, *Whh;
    if (idx_inputs >= 0 && idx_b >= 0 && nw == 2){
        X  = (const float*)d_in[idx_inputs];
        bh = (const float*)d_in[idx_b];
        if (idx_inputs < widx[0]){
            Wxh = (const float*)d_in[widx[0]];
            Whh = (const float*)d_in[widx[1]];
        } else {
            Whh = (const float*)d_in[widx[0]];
            Wxh = (const float*)d_in[widx[1]];
        }
    } else {
        X   = (const float*)d_in[0];
        Wxh = (const float*)d_in[1];
        Whh = (const float*)d_in[2];
        bh  = (const float*)d_in[3];
    }
    float* out = (float*)d_out;                 // [64,1024,256] fp32

    gemm_kernel<<<MM/GR, 256>>>(X, Wxh, bh, out);
    scan2_kernel<<<2*BB, 256>>>(Whh, out);      // 64 clusters of 2 CTAs
}